// round 10
// baseline (speedup 1.0000x reference)
#include <cuda_runtime.h>
#include <cuda_bf16.h>
#include <cstdint>

// ---------------- scratch (static device globals; no allocation allowed) ----
#define N_CAP   50176
#define E_CAP   1000448
#define MAXBLK  64

__device__ uint16_t g_x_hi [N_CAP * 128];
__device__ uint16_t g_x_lo [N_CAP * 128];
__device__ uint16_t g_a1_hi[N_CAP * 128];
__device__ uint16_t g_a1_lo[N_CAP * 128];
__device__ uint16_t g_h1_hi[N_CAP * 256];
__device__ uint16_t g_h1_lo[N_CAP * 256];
__device__ float    g_s2z2 [N_CAP * 256];   // s1 (layer1), then [s2|z2] (layer2)
__device__ uint16_t g_w_hi [131072];        // Ws1 | Wn1 | Ws2 | Wn2
__device__ uint16_t g_w_lo [131072];
__device__ int      g_cnt   [N_CAP];
__device__ int      g_off   [N_CAP + 1];
__device__ int      g_cursor[N_CAP];
__device__ int      g_srt   [E_CAP];
__device__ int      g_bsum  [MAXBLK];

// ---------------- small helpers ----------------------------------------------
__device__ __forceinline__ uint32_t smem_u32(const void* p) {
    uint32_t a;
    asm("{ .reg .u64 t; cvta.to.shared.u64 t, %1; cvt.u32.u64 %0, t; }"
        : "=r"(a) : "l"(p));
    return a;
}
__device__ __forceinline__ void hilo(float v, uint16_t& h, uint16_t& l) {
    __nv_bfloat16 hb = __float2bfloat16(v);
    __nv_bfloat16 lb = __float2bfloat16(v - __bfloat162float(hb));
    h = __bfloat16_as_ushort(hb);
    l = __bfloat16_as_ushort(lb);
}
__device__ __forceinline__ void ldsm_x4(uint32_t* r, uint32_t addr) {
    asm volatile("ldmatrix.sync.aligned.m8n8.x4.shared.b16 {%0,%1,%2,%3}, [%4];"
                 : "=r"(r[0]), "=r"(r[1]), "=r"(r[2]), "=r"(r[3]) : "r"(addr));
}
__device__ __forceinline__ void ldsm_x2(uint32_t* r, uint32_t addr) {
    asm volatile("ldmatrix.sync.aligned.m8n8.x2.shared.b16 {%0,%1}, [%2];"
                 : "=r"(r[0]), "=r"(r[1]) : "r"(addr));
}
__device__ __forceinline__ void mma_bf16(float* d, const uint32_t* a,
                                         const uint32_t* b) {
    asm volatile(
        "mma.sync.aligned.m16n8k16.row.col.f32.bf16.bf16.f32 "
        "{%0,%1,%2,%3}, {%4,%5,%6,%7}, {%8,%9}, {%0,%1,%2,%3};"
        : "+f"(d[0]), "+f"(d[1]), "+f"(d[2]), "+f"(d[3])
        : "r"(a[0]), "r"(a[1]), "r"(a[2]), "r"(a[3]), "r"(b[0]), "r"(b[1]));
}
__device__ __forceinline__ void cp16(uint32_t smem, const void* g, uint32_t sz) {
    asm volatile("cp.async.ca.shared.global [%0], [%1], 16, %2;"
                 :: "r"(smem), "l"(g), "r"(sz) : "memory");
}
#define CP_COMMIT() asm volatile("cp.async.commit_group;" ::: "memory")
#define CP_WAIT1()  asm volatile("cp.async.wait_group 1;" ::: "memory")
#define CP_WAIT0()  asm volatile("cp.async.wait_group 0;" ::: "memory")

// ---------------- CSR build ---------------------------------------------------
__global__ void zero_i(int* __restrict__ p, int n) {
    int i = blockIdx.x * blockDim.x + threadIdx.x;
    if (i < n) p[i] = 0;
}

__global__ void count_kernel(const int* __restrict__ dst, int E, int N,
                             int* __restrict__ cnt) {
    int i = (blockIdx.x * blockDim.x + threadIdx.x) * 2;
    if (i + 1 < E) {
        int2 d2 = *reinterpret_cast<const int2*>(dst + i);
        atomicAdd(&cnt[min(max(d2.x, 0), N - 1)], 1);
        atomicAdd(&cnt[min(max(d2.y, 0), N - 1)], 1);
    } else if (i < E) {
        atomicAdd(&cnt[min(max(dst[i], 0), N - 1)], 1);
    }
}

__global__ void block_sum(const int* __restrict__ cnt, int N,
                          int* __restrict__ bsum) {
    __shared__ int sh[1024];
    int i = blockIdx.x * 1024 + threadIdx.x;
    sh[threadIdx.x] = (i < N) ? cnt[i] : 0;
    __syncthreads();
    for (int d = 512; d > 0; d >>= 1) {
        if (threadIdx.x < d) sh[threadIdx.x] += sh[threadIdx.x + d];
        __syncthreads();
    }
    if (threadIdx.x == 0) bsum[blockIdx.x] = sh[0];
}

__global__ void block_scan(const int* __restrict__ cnt,
                           const int* __restrict__ bsum,
                           int* __restrict__ off, int* __restrict__ cursor,
                           int N) {
    __shared__ int sh[1024];
    __shared__ int carry_s;
    int tid = threadIdx.x;
    if (tid == 0) {
        int a = 0;
        for (int i = 0; i < (int)blockIdx.x; i++) a += bsum[i];
        carry_s = a;
    }
    int i = blockIdx.x * 1024 + tid;
    int v = (i < N) ? cnt[i] : 0;
    sh[tid] = v;
    __syncthreads();
#pragma unroll
    for (int d = 1; d < 1024; d <<= 1) {
        int t = (tid >= d) ? sh[tid - d] : 0;
        __syncthreads();
        sh[tid] += t;
        __syncthreads();
    }
    int incl = sh[tid] + carry_s;
    if (i < N) {
        off[i + 1] = incl;
        cursor[i]  = incl - v;
    }
    if (blockIdx.x == 0 && tid == 0) off[0] = 0;
}

__global__ void scatter_kernel(const int* __restrict__ src,
                               const int* __restrict__ dst, int E, int N,
                               int* __restrict__ cursor, int* __restrict__ srt) {
    int i = (blockIdx.x * blockDim.x + threadIdx.x) * 2;
    if (i + 1 < E) {
        int2 s2 = *reinterpret_cast<const int2*>(src + i);
        int2 d2 = *reinterpret_cast<const int2*>(dst + i);
        int p0 = atomicAdd(&cursor[min(max(d2.x, 0), N - 1)], 1);
        srt[p0] = min(max(s2.x, 0), N - 1);
        int p1 = atomicAdd(&cursor[min(max(d2.y, 0), N - 1)], 1);
        srt[p1] = min(max(s2.y, 0), N - 1);
    } else if (i < E) {
        int p0 = atomicAdd(&cursor[min(max(dst[i], 0), N - 1)], 1);
        srt[p0] = min(max(src[i], 0), N - 1);
    }
}

// ---------------- fp32 -> bf16 hi/lo conversions ------------------------------
__global__ void conv_hilo(const float* __restrict__ s, uint16_t* __restrict__ hi,
                          uint16_t* __restrict__ lo, int n) {
    int i = blockIdx.x * blockDim.x + threadIdx.x;
    if (i < n) hilo(s[i], hi[i], lo[i]);
}

__global__ void conv_w(const float* __restrict__ w0, const float* __restrict__ w1,
                       const float* __restrict__ w2, const float* __restrict__ w3,
                       uint16_t* __restrict__ hi, uint16_t* __restrict__ lo) {
    int i = blockIdx.x * blockDim.x + threadIdx.x;
    if (i >= 131072) return;
    int which = i >> 15, idx = i & 32767;
    const float* w = (which == 0) ? w0 : (which == 1) ? w1
                   : (which == 2) ? w2 : w3;
    hilo(w[idx], hi[i], lo[i]);
}

// ---------------- gather aggregation (layer 1): x fp32 -> a1 hi/lo -------------
__global__ void gather1(const float* __restrict__ x,
                        const int* __restrict__ srt,
                        const int* __restrict__ off,
                        uint16_t* __restrict__ hi, uint16_t* __restrict__ lo,
                        int N) {
    int warp = (blockIdx.x * blockDim.x + threadIdx.x) >> 5;
    int lane = threadIdx.x & 31;
    if (warp >= N) return;
    int s0 = off[warp], s1 = off[warp + 1];

    float4 acc = make_float4(0.f, 0.f, 0.f, 0.f);
    int e = s0;
    for (; e + 1 < s1; e += 2) {
        int sA = srt[e], sB = srt[e + 1];
        float4 a = *reinterpret_cast<const float4*>(x + (size_t)sA * 128 + lane * 4);
        float4 b = *reinterpret_cast<const float4*>(x + (size_t)sB * 128 + lane * 4);
        acc.x += a.x + b.x; acc.y += a.y + b.y;
        acc.z += a.z + b.z; acc.w += a.w + b.w;
    }
    if (e < s1) {
        int sA = srt[e];
        float4 a = *reinterpret_cast<const float4*>(x + (size_t)sA * 128 + lane * 4);
        acc.x += a.x; acc.y += a.y; acc.z += a.z; acc.w += a.w;
    }

    float r = (s1 > s0) ? 1.0f / (float)(s1 - s0) : 0.0f;
    acc.x *= r; acc.y *= r; acc.z *= r; acc.w *= r;

    uint16_t h0, l0, h1v, l1, h2, l2, h3, l3;
    hilo(acc.x, h0, l0); hilo(acc.y, h1v, l1);
    hilo(acc.z, h2, l2); hilo(acc.w, h3, l3);
    size_t base = (size_t)warp * 128 + lane * 4;
    *reinterpret_cast<uint2*>(hi + base) =
        make_uint2((uint32_t)h0 | ((uint32_t)h1v << 16),
                   (uint32_t)h2 | ((uint32_t)h3 << 16));
    *reinterpret_cast<uint2*>(lo + base) =
        make_uint2((uint32_t)l0 | ((uint32_t)l1 << 16),
                   (uint32_t)l2 | ((uint32_t)l3 << 16));
}

// ---------------- fused layer-2 finish: out = relu(s2 + agg(z2) + b2) ---------
__global__ void gather_out(const float* __restrict__ s2z2,
                           const int* __restrict__ srt,
                           const int* __restrict__ off,
                           const float* __restrict__ bias,
                           float* __restrict__ out, int N) {
    int warp = (blockIdx.x * blockDim.x + threadIdx.x) >> 5;
    int lane = threadIdx.x & 31;
    if (warp >= N) return;
    int s0 = off[warp], s1 = off[warp + 1];

    float4 acc = make_float4(0.f, 0.f, 0.f, 0.f);
    int e = s0;
    for (; e + 1 < s1; e += 2) {
        int sA = srt[e], sB = srt[e + 1];
        float4 a = *reinterpret_cast<const float4*>(
            s2z2 + (size_t)sA * 256 + 128 + lane * 4);
        float4 b = *reinterpret_cast<const float4*>(
            s2z2 + (size_t)sB * 256 + 128 + lane * 4);
        acc.x += a.x + b.x; acc.y += a.y + b.y;
        acc.z += a.z + b.z; acc.w += a.w + b.w;
    }
    if (e < s1) {
        int sA = srt[e];
        float4 a = *reinterpret_cast<const float4*>(
            s2z2 + (size_t)sA * 256 + 128 + lane * 4);
        acc.x += a.x; acc.y += a.y; acc.z += a.z; acc.w += a.w;
    }

    float r = (s1 > s0) ? 1.0f / (float)(s1 - s0) : 0.0f;
    float4 s = *reinterpret_cast<const float4*>(s2z2 + (size_t)warp * 256 + lane * 4);
    float4 b = *reinterpret_cast<const float4*>(bias + lane * 4);
    float4 o;
    o.x = fmaxf(s.x + acc.x * r + b.x, 0.f);
    o.y = fmaxf(s.y + acc.y * r + b.y, 0.f);
    o.z = fmaxf(s.z + acc.z * r + b.z, 0.f);
    o.w = fmaxf(s.w + acc.w * r + b.w, 0.f);
    *reinterpret_cast<float4*>(out + (size_t)warp * 128 + lane * 4) = o;
}

// ---------------- bf16x3 GEMM, cp.async double-buffered ------------------------
// OUTMODE 0: raw fp32 out. OUTMODE 2: relu(acc + Cin + bias) -> hi/lo bf16.
struct Seg { const uint16_t *ahi, *alo, *bhi, *blo; };

#define T_BYTES 10240
#define STAGE   (4 * T_BYTES)

template <int SEGD, int OUTMODE>
__global__ void __launch_bounds__(256, 2)
gemm3(Seg s0, int M, const float* __restrict__ bias,
      const float* __restrict__ Cin,
      float* __restrict__ C, uint16_t* __restrict__ Chi,
      uint16_t* __restrict__ Clo, int ldc) {
    extern __shared__ char dsm[];
    uint32_t sb = smem_u32(dsm);

    int tid = threadIdx.x;
    int wid = tid >> 5;
    int lane = tid & 31;
    int rowBase = blockIdx.y * 128;
    int colBase = blockIdx.x * 128;
    int warp_m = (wid & 3) * 32;
    int warp_n = (wid >> 2) * 64;

    float acc[2][8][4] = {};

    constexpr int NITER = SEGD / 32;

    auto load_stage = [&](int it, int buf) {
        int kin = it * 32;
        uint32_t sbase = sb + buf * STAGE;
#pragma unroll
        for (int h = 0; h < 2; h++) {
            int f  = tid + h * 256;
            int r  = f >> 2;
            int c8 = (f & 3) * 8;
            int gm = rowBase + r;
            uint32_t asz = (gm < M) ? 16u : 0u;
            int gmc = min(gm, M - 1);
            uint32_t so = sbase + (uint32_t)(r * 40 + c8) * 2;
            size_t ao = (size_t)gmc * SEGD + kin + c8;
            cp16(so,               s0.ahi + ao, asz);
            cp16(so + T_BYTES,     s0.alo + ao, asz);
            size_t bo = (size_t)(colBase + r) * SEGD + kin + c8;
            cp16(so + 2 * T_BYTES, s0.bhi + bo, 16);
            cp16(so + 3 * T_BYTES, s0.blo + bo, 16);
        }
        CP_COMMIT();
    };

    load_stage(0, 0);

    for (int it = 0; it < NITER; it++) {
        if (it + 1 < NITER) {
            load_stage(it + 1, (it + 1) & 1);
            CP_WAIT1();
        } else {
            CP_WAIT0();
        }
        __syncthreads();

        uint32_t sbase = sb + (it & 1) * STAGE;
        uint32_t asH = sbase, asL = sbase + T_BYTES;
        uint32_t bsH = sbase + 2 * T_BYTES, bsL = sbase + 3 * T_BYTES;

#pragma unroll
        for (int ks = 0; ks < 32; ks += 16) {
            uint32_t bH[8][2], bL[8][2];
#pragma unroll
            for (int nt = 0; nt < 8; nt++) {
                uint32_t roff = (uint32_t)((warp_n + nt * 8 + (lane & 7)) * 40 +
                                           ks + ((lane >> 3) & 1) * 8) * 2;
                ldsm_x2(bH[nt], bsH + roff);
                ldsm_x2(bL[nt], bsL + roff);
            }
#pragma unroll
            for (int mt = 0; mt < 2; mt++) {
                uint32_t aH[4], aL[4];
                uint32_t roff = (uint32_t)((warp_m + mt * 16 + (lane & 15)) * 40 +
                                           ks + (lane >> 4) * 8) * 2;
                ldsm_x4(aH, asH + roff);
                ldsm_x4(aL, asL + roff);
#pragma unroll
                for (int nt = 0; nt < 8; nt++) {
                    mma_bf16(acc[mt][nt], aH, bH[nt]);
                    mma_bf16(acc[mt][nt], aH, bL[nt]);
                    mma_bf16(acc[mt][nt], aL, bH[nt]);
                }
            }
        }
        __syncthreads();
    }

    // epilogue
#pragma unroll
    for (int mt = 0; mt < 2; mt++) {
        int gm0 = rowBase + warp_m + mt * 16 + (lane >> 2);
#pragma unroll
        for (int nt = 0; nt < 8; nt++) {
            int n = colBase + warp_n + nt * 8 + (lane & 3) * 2;
#pragma unroll
            for (int half = 0; half < 2; half++) {
                int gm = gm0 + half * 8;
                if (gm >= M) continue;
                float v0 = acc[mt][nt][half * 2 + 0];
                float v1 = acc[mt][nt][half * 2 + 1];
                if (OUTMODE == 2) {
                    float2 ci = *reinterpret_cast<const float2*>(
                        Cin + (size_t)gm * ldc + n);
                    v0 = fmaxf(v0 + ci.x + bias[n], 0.f);
                    v1 = fmaxf(v1 + ci.y + bias[n + 1], 0.f);
                    uint16_t h0, l0, h1v, l1;
                    hilo(v0, h0, l0); hilo(v1, h1v, l1);
                    *reinterpret_cast<uint32_t*>(Chi + (size_t)gm * ldc + n) =
                        (uint32_t)h0 | ((uint32_t)h1v << 16);
                    *reinterpret_cast<uint32_t*>(Clo + (size_t)gm * ldc + n) =
                        (uint32_t)l0 | ((uint32_t)l1 << 16);
                } else {
                    *reinterpret_cast<float2*>(C + (size_t)gm * ldc + n) =
                        make_float2(v0, v1);
                }
            }
        }
    }
}

// ---------------- launch -------------------------------------------------------
extern "C" void kernel_launch(void* const* d_in, const int* in_sizes, int n_in,
                              void* d_out, int out_size) {
    const float* x   = (const float*)d_in[0];
    const int*   ei  = (const int*)d_in[1];
    const float* Ws1 = (const float*)d_in[2];
    const float* Wn1 = (const float*)d_in[3];
    const float* b1  = (const float*)d_in[4];
    const float* Ws2 = (const float*)d_in[5];
    const float* Wn2 = (const float*)d_in[6];
    const float* b2  = (const float*)d_in[7];
    float*       out = (float*)d_out;

    const int H     = in_sizes[4];             // 256
    const int F_IN  = in_sizes[2] / H;         // 128
    const int N     = in_sizes[0] / F_IN;      // 50000
    const int E     = in_sizes[1] / 2;         // 800000
    const int F_OUT = in_sizes[7];             // 128
    (void)F_OUT;

    const int* src = ei;
    const int* dst = ei + E;

    uint16_t *x_hi, *x_lo, *a1_hi, *a1_lo, *h1_hi, *h1_lo, *w_hi, *w_lo;
    float *s2z2;
    int *cnt, *off, *cursor, *srt, *bsum;
    cudaGetSymbolAddress((void**)&x_hi,  g_x_hi);
    cudaGetSymbolAddress((void**)&x_lo,  g_x_lo);
    cudaGetSymbolAddress((void**)&a1_hi, g_a1_hi);
    cudaGetSymbolAddress((void**)&a1_lo, g_a1_lo);
    cudaGetSymbolAddress((void**)&h1_hi, g_h1_hi);
    cudaGetSymbolAddress((void**)&h1_lo, g_h1_lo);
    cudaGetSymbolAddress((void**)&w_hi,  g_w_hi);
    cudaGetSymbolAddress((void**)&w_lo,  g_w_lo);
    cudaGetSymbolAddress((void**)&s2z2,  g_s2z2);
    cudaGetSymbolAddress((void**)&cnt,    g_cnt);
    cudaGetSymbolAddress((void**)&off,    g_off);
    cudaGetSymbolAddress((void**)&cursor, g_cursor);
    cudaGetSymbolAddress((void**)&srt,    g_srt);
    cudaGetSymbolAddress((void**)&bsum,   g_bsum);

    // one-time infra (created outside graph capture on the correctness call)
    static cudaStream_t s2 = nullptr;
    static cudaEvent_t evF = nullptr, evJ = nullptr;
    if (!s2) {
        cudaStreamCreateWithFlags(&s2, cudaStreamNonBlocking);
        cudaEventCreateWithFlags(&evF, cudaEventDisableTiming);
        cudaEventCreateWithFlags(&evJ, cudaEventDisableTiming);
    }

    const int nb = (N + 1023) / 1024;
    const int DSMEM = 2 * STAGE;   // 81920

    cudaFuncSetAttribute(gemm3<128, 0>,
                         cudaFuncAttributeMaxDynamicSharedMemorySize, DSMEM);
    cudaFuncSetAttribute(gemm3<128, 2>,
                         cudaFuncAttributeMaxDynamicSharedMemorySize, DSMEM);
    cudaFuncSetAttribute(gemm3<256, 0>,
                         cudaFuncAttributeMaxDynamicSharedMemorySize, DSMEM);

    // ---- fork: stream s2 does conversions + s1 GEMM (graph-independent) ----
    cudaEventRecord(evF, 0);
    cudaStreamWaitEvent(s2, evF, 0);

    conv_hilo<<<(N * F_IN + 255) / 256, 256, 0, s2>>>(x, x_hi, x_lo, N * F_IN);
    conv_w<<<512, 256, 0, s2>>>(Ws1, Wn1, Ws2, Wn2, w_hi, w_lo);
    {   // s1 = x Ws1^T  (raw fp32 into s2z2, ldc = 256)
        Seg sA{x_hi, x_lo, w_hi, w_lo};
        dim3 grid(H / 128, (N + 127) / 128);
        gemm3<128, 0><<<grid, 256, DSMEM, s2>>>(sA, N, nullptr, nullptr,
                                                s2z2, nullptr, nullptr, H);
    }
    cudaEventRecord(evJ, s2);

    // ---- main stream: CSR build + layer-1 gather (runs concurrently) ----
    zero_i<<<(N + 255) / 256, 256>>>(cnt, N);
    count_kernel<<<(E / 2 + 255) / 256, 256>>>(dst, E, N, cnt);
    block_sum<<<nb, 1024>>>(cnt, N, bsum);
    block_scan<<<nb, 1024>>>(cnt, bsum, off, cursor, N);
    scatter_kernel<<<(E / 2 + 255) / 256, 256>>>(src, dst, E, N, cursor, srt);
    gather1<<<(N * 32 + 255) / 256, 256>>>(x, srt, off, a1_hi, a1_lo, N);

    // ---- join ----
    cudaStreamWaitEvent(0, evJ, 0);

    // GEMM1b: h1 = relu(a1 Wn1^T + s1 + b1) -> h1 hi/lo (ldc = 256)
    {
        Seg sA{a1_hi, a1_lo, w_hi + 32768, w_lo + 32768};
        dim3 grid(H / 128, (N + 127) / 128);
        gemm3<128, 2><<<grid, 256, DSMEM>>>(sA, N, b1, s2z2, nullptr,
                                            h1_hi, h1_lo, H);
    }

    // GEMM2: [s2|z2] = h1 [Ws2;Wn2]^T (raw fp32, ldc = 256; overwrites s1)
    {
        Seg sA{h1_hi, h1_lo, w_hi + 65536, w_lo + 65536};
        dim3 grid(2, (N + 127) / 128);
        gemm3<256, 0><<<grid, 256, DSMEM>>>(sA, N, nullptr, nullptr,
                                            s2z2, nullptr, nullptr, 256);
    }

    // fused: out = relu(s2 + agg(z2) + b2)
    gather_out<<<(N * 32 + 255) / 256, 256>>>(s2z2, srt, off, b2, out, N);
}

// round 11
// speedup vs baseline: 1.0408x; 1.0408x over previous
#include <cuda_runtime.h>
#include <cuda_bf16.h>
#include <cstdint>

// ---------------- scratch (static device globals; no allocation allowed) ----
#define N_CAP   50176
#define E_CAP   1000448
#define MAXBLK  64

__device__ uint16_t g_x_hi [N_CAP * 128];
__device__ uint16_t g_x_lo [N_CAP * 128];
__device__ uint16_t g_a1_hi[N_CAP * 128];
__device__ uint16_t g_a1_lo[N_CAP * 128];
__device__ uint16_t g_h1_hi[N_CAP * 256];
__device__ uint16_t g_h1_lo[N_CAP * 256];
__device__ float    g_s2z2 [N_CAP * 256];   // [s2 | z2] fp32
__device__ uint16_t g_w_hi [131072];        // Ws1 | Wn1 | w2cat
__device__ uint16_t g_w_lo [131072];
__device__ int      g_cnt   [N_CAP];
__device__ int      g_off   [N_CAP + 1];
__device__ int      g_cursor[N_CAP];
__device__ int      g_srt   [E_CAP];
__device__ int      g_bsum  [MAXBLK];

// ---------------- small helpers ----------------------------------------------
__device__ __forceinline__ uint32_t smem_u32(const void* p) {
    uint32_t a;
    asm("{ .reg .u64 t; cvta.to.shared.u64 t, %1; cvt.u32.u64 %0, t; }"
        : "=r"(a) : "l"(p));
    return a;
}
__device__ __forceinline__ void hilo(float v, uint16_t& h, uint16_t& l) {
    __nv_bfloat16 hb = __float2bfloat16(v);
    __nv_bfloat16 lb = __float2bfloat16(v - __bfloat162float(hb));
    h = __bfloat16_as_ushort(hb);
    l = __bfloat16_as_ushort(lb);
}
__device__ __forceinline__ void ldsm_x4(uint32_t* r, uint32_t addr) {
    asm volatile("ldmatrix.sync.aligned.m8n8.x4.shared.b16 {%0,%1,%2,%3}, [%4];"
                 : "=r"(r[0]), "=r"(r[1]), "=r"(r[2]), "=r"(r[3]) : "r"(addr));
}
__device__ __forceinline__ void ldsm_x2(uint32_t* r, uint32_t addr) {
    asm volatile("ldmatrix.sync.aligned.m8n8.x2.shared.b16 {%0,%1}, [%2];"
                 : "=r"(r[0]), "=r"(r[1]) : "r"(addr));
}
__device__ __forceinline__ void mma_bf16(float* d, const uint32_t* a,
                                         const uint32_t* b) {
    asm volatile(
        "mma.sync.aligned.m16n8k16.row.col.f32.bf16.bf16.f32 "
        "{%0,%1,%2,%3}, {%4,%5,%6,%7}, {%8,%9}, {%0,%1,%2,%3};"
        : "+f"(d[0]), "+f"(d[1]), "+f"(d[2]), "+f"(d[3])
        : "r"(a[0]), "r"(a[1]), "r"(a[2]), "r"(a[3]), "r"(b[0]), "r"(b[1]));
}
__device__ __forceinline__ void cp16(uint32_t smem, const void* g, uint32_t sz) {
    asm volatile("cp.async.ca.shared.global [%0], [%1], 16, %2;"
                 :: "r"(smem), "l"(g), "r"(sz) : "memory");
}
#define CP_COMMIT() asm volatile("cp.async.commit_group;" ::: "memory")
#define CP_WAIT1()  asm volatile("cp.async.wait_group 1;" ::: "memory")
#define CP_WAIT0()  asm volatile("cp.async.wait_group 0;" ::: "memory")

// ---------------- CSR build ---------------------------------------------------
__global__ void zero_i4(int4* __restrict__ p, int n4) {
    int i = blockIdx.x * blockDim.x + threadIdx.x;
    if (i < n4) p[i] = make_int4(0, 0, 0, 0);
}

__global__ void count_kernel(const int* __restrict__ dst, int E, int N,
                             int* __restrict__ cnt) {
    int i = (blockIdx.x * blockDim.x + threadIdx.x) * 2;
    if (i + 1 < E) {
        int2 d2 = *reinterpret_cast<const int2*>(dst + i);
        atomicAdd(&cnt[min(max(d2.x, 0), N - 1)], 1);
        atomicAdd(&cnt[min(max(d2.y, 0), N - 1)], 1);
    } else if (i < E) {
        atomicAdd(&cnt[min(max(dst[i], 0), N - 1)], 1);
    }
}

__global__ void block_sum(const int* __restrict__ cnt, int N,
                          int* __restrict__ bsum) {
    __shared__ int sh[1024];
    int i = blockIdx.x * 1024 + threadIdx.x;
    sh[threadIdx.x] = (i < N) ? cnt[i] : 0;
    __syncthreads();
    for (int d = 512; d > 0; d >>= 1) {
        if (threadIdx.x < d) sh[threadIdx.x] += sh[threadIdx.x + d];
        __syncthreads();
    }
    if (threadIdx.x == 0) bsum[blockIdx.x] = sh[0];
}

__global__ void block_scan(const int* __restrict__ cnt,
                           const int* __restrict__ bsum,
                           int* __restrict__ off, int* __restrict__ cursor,
                           int N) {
    __shared__ int sh[1024];
    __shared__ int carry_s;
    int tid = threadIdx.x;
    if (tid == 0) {
        int a = 0;
        for (int i = 0; i < (int)blockIdx.x; i++) a += bsum[i];
        carry_s = a;
    }
    int i = blockIdx.x * 1024 + tid;
    int v = (i < N) ? cnt[i] : 0;
    sh[tid] = v;
    __syncthreads();
#pragma unroll
    for (int d = 1; d < 1024; d <<= 1) {
        int t = (tid >= d) ? sh[tid - d] : 0;
        __syncthreads();
        sh[tid] += t;
        __syncthreads();
    }
    int incl = sh[tid] + carry_s;
    if (i < N) {
        off[i + 1] = incl;
        cursor[i]  = incl - v;
    }
    if (blockIdx.x == 0 && tid == 0) off[0] = 0;
}

__global__ void scatter_kernel(const int* __restrict__ src,
                               const int* __restrict__ dst, int E, int N,
                               int* __restrict__ cursor, int* __restrict__ srt) {
    int i = (blockIdx.x * blockDim.x + threadIdx.x) * 2;
    if (i + 1 < E) {
        int2 s2 = *reinterpret_cast<const int2*>(src + i);
        int2 d2 = *reinterpret_cast<const int2*>(dst + i);
        int p0 = atomicAdd(&cursor[min(max(d2.x, 0), N - 1)], 1);
        srt[p0] = min(max(s2.x, 0), N - 1);
        int p1 = atomicAdd(&cursor[min(max(d2.y, 0), N - 1)], 1);
        srt[p1] = min(max(s2.y, 0), N - 1);
    } else if (i < E) {
        int p0 = atomicAdd(&cursor[min(max(dst[i], 0), N - 1)], 1);
        srt[p0] = min(max(src[i], 0), N - 1);
    }
}

// ---------------- fp32 -> bf16 hi/lo conversions ------------------------------
__global__ void conv_hilo(const float* __restrict__ s, uint16_t* __restrict__ hi,
                          uint16_t* __restrict__ lo, int n) {
    int i = blockIdx.x * blockDim.x + threadIdx.x;
    if (i < n) hilo(s[i], hi[i], lo[i]);
}

__global__ void conv_w(const float* __restrict__ w0, const float* __restrict__ w1,
                       const float* __restrict__ w2, const float* __restrict__ w3,
                       uint16_t* __restrict__ hi, uint16_t* __restrict__ lo) {
    int i = blockIdx.x * blockDim.x + threadIdx.x;
    if (i >= 131072) return;
    int which = i >> 15, idx = i & 32767;
    const float* w = (which == 0) ? w0 : (which == 1) ? w1
                   : (which == 2) ? w2 : w3;
    hilo(w[idx], hi[i], lo[i]);
}

// ---------------- gather aggregation (layer 1): x fp32 -> a1 hi/lo -------------
__global__ void gather1(const float* __restrict__ x,
                        const int* __restrict__ srt,
                        const int* __restrict__ off,
                        uint16_t* __restrict__ hi, uint16_t* __restrict__ lo,
                        int N) {
    int warp = (blockIdx.x * blockDim.x + threadIdx.x) >> 5;
    int lane = threadIdx.x & 31;
    if (warp >= N) return;
    int s0 = off[warp], s1 = off[warp + 1];

    float4 acc = make_float4(0.f, 0.f, 0.f, 0.f);
    int e = s0;
    for (; e + 1 < s1; e += 2) {
        int sA = srt[e], sB = srt[e + 1];
        float4 a = *reinterpret_cast<const float4*>(x + (size_t)sA * 128 + lane * 4);
        float4 b = *reinterpret_cast<const float4*>(x + (size_t)sB * 128 + lane * 4);
        acc.x += a.x + b.x; acc.y += a.y + b.y;
        acc.z += a.z + b.z; acc.w += a.w + b.w;
    }
    if (e < s1) {
        int sA = srt[e];
        float4 a = *reinterpret_cast<const float4*>(x + (size_t)sA * 128 + lane * 4);
        acc.x += a.x; acc.y += a.y; acc.z += a.z; acc.w += a.w;
    }

    float r = (s1 > s0) ? 1.0f / (float)(s1 - s0) : 0.0f;
    acc.x *= r; acc.y *= r; acc.z *= r; acc.w *= r;

    uint16_t h0, l0, h1v, l1, h2, l2, h3, l3;
    hilo(acc.x, h0, l0); hilo(acc.y, h1v, l1);
    hilo(acc.z, h2, l2); hilo(acc.w, h3, l3);
    size_t base = (size_t)warp * 128 + lane * 4;
    *reinterpret_cast<uint2*>(hi + base) =
        make_uint2((uint32_t)h0 | ((uint32_t)h1v << 16),
                   (uint32_t)h2 | ((uint32_t)h3 << 16));
    *reinterpret_cast<uint2*>(lo + base) =
        make_uint2((uint32_t)l0 | ((uint32_t)l1 << 16),
                   (uint32_t)l2 | ((uint32_t)l3 << 16));
}

// ---------------- fused layer-2 finish: out = relu(s2 + agg(z2) + b2) ---------
__global__ void gather_out(const float* __restrict__ s2z2,
                           const int* __restrict__ srt,
                           const int* __restrict__ off,
                           const float* __restrict__ bias,
                           float* __restrict__ out, int N) {
    int warp = (blockIdx.x * blockDim.x + threadIdx.x) >> 5;
    int lane = threadIdx.x & 31;
    if (warp >= N) return;
    int s0 = off[warp], s1 = off[warp + 1];

    float4 acc = make_float4(0.f, 0.f, 0.f, 0.f);
    int e = s0;
    for (; e + 1 < s1; e += 2) {
        int sA = srt[e], sB = srt[e + 1];
        float4 a = *reinterpret_cast<const float4*>(
            s2z2 + (size_t)sA * 256 + 128 + lane * 4);
        float4 b = *reinterpret_cast<const float4*>(
            s2z2 + (size_t)sB * 256 + 128 + lane * 4);
        acc.x += a.x + b.x; acc.y += a.y + b.y;
        acc.z += a.z + b.z; acc.w += a.w + b.w;
    }
    if (e < s1) {
        int sA = srt[e];
        float4 a = *reinterpret_cast<const float4*>(
            s2z2 + (size_t)sA * 256 + 128 + lane * 4);
        acc.x += a.x; acc.y += a.y; acc.z += a.z; acc.w += a.w;
    }

    float r = (s1 > s0) ? 1.0f / (float)(s1 - s0) : 0.0f;
    float4 s = *reinterpret_cast<const float4*>(s2z2 + (size_t)warp * 256 + lane * 4);
    float4 b = *reinterpret_cast<const float4*>(bias + lane * 4);
    float4 o;
    o.x = fmaxf(s.x + acc.x * r + b.x, 0.f);
    o.y = fmaxf(s.y + acc.y * r + b.y, 0.f);
    o.z = fmaxf(s.z + acc.z * r + b.z, 0.f);
    o.w = fmaxf(s.w + acc.w * r + b.w, 0.f);
    *reinterpret_cast<float4*>(out + (size_t)warp * 128 + lane * 4) = o;
}

// ---------------- bf16x3 GEMM, 128x256 tile, 512 threads, cp.async x2 ---------
// OUTMODE 0: raw fp32 out. OUTMODE 1: relu(acc + bias) -> hi/lo bf16.
struct Seg { const uint16_t *ahi, *alo, *bhi, *blo; };

#define A_BYTES 10240            // 128 rows * 40 cols * 2B
#define B_BYTES 20480            // 256 rows * 40 cols * 2B
#define STAGE   (2 * A_BYTES + 2 * B_BYTES)   // 61440

template <int NSEG, int SEGD, int OUTMODE>
__global__ void __launch_bounds__(512, 1)
gemm3(Seg s0, Seg s1, int M, const float* __restrict__ bias,
      float* __restrict__ C, uint16_t* __restrict__ Chi,
      uint16_t* __restrict__ Clo) {
    extern __shared__ char dsm[];
    uint32_t sb = smem_u32(dsm);

    int tid = threadIdx.x;
    int wid = tid >> 5;
    int lane = tid & 31;
    int rowBase = blockIdx.x * 128;
    int warp_m = (wid & 3) * 32;         // 4 warps over M=128
    int warp_n = (wid >> 2) * 64;        // 4 warps over N=256

    float acc[2][8][4] = {};

    constexpr int ITER_PER_SEG = SEGD / 32;
    constexpr int NITER = NSEG * ITER_PER_SEG;

    auto load_stage = [&](int it, int buf) {
        Seg sg = (NSEG == 1 || it < ITER_PER_SEG) ? s0 : s1;
        int kin = (it % ITER_PER_SEG) * 32;
        uint32_t sbase = sb + buf * STAGE;
        {   // A: 128 rows x 32 cols, 512 threads -> 1 cp16 per tile
            int r  = tid >> 2;
            int c8 = (tid & 3) * 8;
            int gm = rowBase + r;
            uint32_t asz = (gm < M) ? 16u : 0u;
            int gmc = min(gm, M - 1);
            uint32_t so = sbase + (uint32_t)(r * 40 + c8) * 2;
            size_t ao = (size_t)gmc * SEGD + kin + c8;
            cp16(so,           sg.ahi + ao, asz);
            cp16(so + A_BYTES, sg.alo + ao, asz);
        }
#pragma unroll
        for (int h = 0; h < 2; h++) {   // B: 256 rows x 32 cols
            int f  = tid + h * 512;
            int r  = f >> 2;
            int c8 = (f & 3) * 8;
            uint32_t so = sbase + 2 * A_BYTES + (uint32_t)(r * 40 + c8) * 2;
            size_t bo = (size_t)r * SEGD + kin + c8;
            cp16(so,           sg.bhi + bo, 16);
            cp16(so + B_BYTES, sg.blo + bo, 16);
        }
        CP_COMMIT();
    };

    load_stage(0, 0);

    for (int it = 0; it < NITER; it++) {
        if (it + 1 < NITER) {
            load_stage(it + 1, (it + 1) & 1);
            CP_WAIT1();
        } else {
            CP_WAIT0();
        }
        __syncthreads();

        uint32_t sbase = sb + (it & 1) * STAGE;
        uint32_t asH = sbase, asL = sbase + A_BYTES;
        uint32_t bsH = sbase + 2 * A_BYTES, bsL = bsH + B_BYTES;

#pragma unroll
        for (int ks = 0; ks < 32; ks += 16) {
            uint32_t aH2[2][4], aL2[2][4];
#pragma unroll
            for (int mt = 0; mt < 2; mt++) {
                uint32_t roff = (uint32_t)((warp_m + mt * 16 + (lane & 15)) * 40 +
                                           ks + (lane >> 4) * 8) * 2;
                ldsm_x4(aH2[mt], asH + roff);
                ldsm_x4(aL2[mt], asL + roff);
            }
#pragma unroll
            for (int nt = 0; nt < 8; nt++) {
                uint32_t bH[2], bL[2];
                uint32_t roff = (uint32_t)((warp_n + nt * 8 + (lane & 7)) * 40 +
                                           ks + ((lane >> 3) & 1) * 8) * 2;
                ldsm_x2(bH, bsH + roff);
                ldsm_x2(bL, bsL + roff);
#pragma unroll
                for (int mt = 0; mt < 2; mt++) {
                    mma_bf16(acc[mt][nt], aH2[mt], bH);
                    mma_bf16(acc[mt][nt], aH2[mt], bL);
                    mma_bf16(acc[mt][nt], aL2[mt], bH);
                }
            }
        }
        __syncthreads();
    }

    // epilogue (ldc = 256)
#pragma unroll
    for (int mt = 0; mt < 2; mt++) {
        int gm0 = rowBase + warp_m + mt * 16 + (lane >> 2);
#pragma unroll
        for (int nt = 0; nt < 8; nt++) {
            int n = warp_n + nt * 8 + (lane & 3) * 2;
#pragma unroll
            for (int half = 0; half < 2; half++) {
                int gm = gm0 + half * 8;
                if (gm >= M) continue;
                float v0 = acc[mt][nt][half * 2 + 0];
                float v1 = acc[mt][nt][half * 2 + 1];
                if (OUTMODE == 1) {
                    v0 = fmaxf(v0 + bias[n], 0.f);
                    v1 = fmaxf(v1 + bias[n + 1], 0.f);
                    uint16_t h0, l0, h1v, l1;
                    hilo(v0, h0, l0); hilo(v1, h1v, l1);
                    *reinterpret_cast<uint32_t*>(Chi + (size_t)gm * 256 + n) =
                        (uint32_t)h0 | ((uint32_t)h1v << 16);
                    *reinterpret_cast<uint32_t*>(Clo + (size_t)gm * 256 + n) =
                        (uint32_t)l0 | ((uint32_t)l1 << 16);
                } else {
                    *reinterpret_cast<float2*>(C + (size_t)gm * 256 + n) =
                        make_float2(v0, v1);
                }
            }
        }
    }
}

// ---------------- launch -------------------------------------------------------
extern "C" void kernel_launch(void* const* d_in, const int* in_sizes, int n_in,
                              void* d_out, int out_size) {
    const float* x   = (const float*)d_in[0];
    const int*   ei  = (const int*)d_in[1];
    const float* Ws1 = (const float*)d_in[2];
    const float* Wn1 = (const float*)d_in[3];
    const float* b1  = (const float*)d_in[4];
    const float* Ws2 = (const float*)d_in[5];
    const float* Wn2 = (const float*)d_in[6];
    const float* b2  = (const float*)d_in[7];
    float*       out = (float*)d_out;

    const int H     = in_sizes[4];             // 256
    const int F_IN  = in_sizes[2] / H;         // 128
    const int N     = in_sizes[0] / F_IN;      // 50000
    const int E     = in_sizes[1] / 2;         // 800000

    const int* src = ei;
    const int* dst = ei + E;

    uint16_t *x_hi, *x_lo, *a1_hi, *a1_lo, *h1_hi, *h1_lo, *w_hi, *w_lo;
    float *s2z2;
    int *cnt, *off, *cursor, *srt, *bsum;
    cudaGetSymbolAddress((void**)&x_hi,  g_x_hi);
    cudaGetSymbolAddress((void**)&x_lo,  g_x_lo);
    cudaGetSymbolAddress((void**)&a1_hi, g_a1_hi);
    cudaGetSymbolAddress((void**)&a1_lo, g_a1_lo);
    cudaGetSymbolAddress((void**)&h1_hi, g_h1_hi);
    cudaGetSymbolAddress((void**)&h1_lo, g_h1_lo);
    cudaGetSymbolAddress((void**)&w_hi,  g_w_hi);
    cudaGetSymbolAddress((void**)&w_lo,  g_w_lo);
    cudaGetSymbolAddress((void**)&s2z2,  g_s2z2);
    cudaGetSymbolAddress((void**)&cnt,    g_cnt);
    cudaGetSymbolAddress((void**)&off,    g_off);
    cudaGetSymbolAddress((void**)&cursor, g_cursor);
    cudaGetSymbolAddress((void**)&srt,    g_srt);
    cudaGetSymbolAddress((void**)&bsum,   g_bsum);

    const int nb = (N + 1023) / 1024;
    const int DSMEM = 2 * STAGE;   // 122880

    cudaFuncSetAttribute(gemm3<2, 128, 1>,
                         cudaFuncAttributeMaxDynamicSharedMemorySize, DSMEM);
    cudaFuncSetAttribute(gemm3<1, 256, 0>,
                         cudaFuncAttributeMaxDynamicSharedMemorySize, DSMEM);

    // 1) CSR build
    zero_i4<<<(N / 4 + 255) / 256, 256>>>((int4*)cnt, N / 4);
    count_kernel<<<(E / 2 + 255) / 256, 256>>>(dst, E, N, cnt);
    block_sum<<<nb, 1024>>>(cnt, N, bsum);
    block_scan<<<nb, 1024>>>(cnt, bsum, off, cursor, N);
    scatter_kernel<<<(E / 2 + 255) / 256, 256>>>(src, dst, E, N, cursor, srt);

    // 2) hi/lo conversions
    conv_hilo<<<(N * F_IN + 255) / 256, 256>>>(x, x_hi, x_lo, N * F_IN);
    conv_w<<<512, 256>>>(Ws1, Wn1, Ws2, Wn2, w_hi, w_lo);

    // 3) layer-1 aggregation -> a1 hi/lo
    gather1<<<(N * 32 + 255) / 256, 256>>>(x, srt, off, a1_hi, a1_lo, N);

    // 4) GEMM1: h1 = relu(x Ws1^T + a1 Wn1^T + b1) -> h1 hi/lo
    {
        Seg sA{x_hi, x_lo, w_hi, w_lo};
        Seg sB{a1_hi, a1_lo, w_hi + 32768, w_lo + 32768};
        gemm3<2, 128, 1><<<(N + 127) / 128, 512, DSMEM>>>(sA, sB, N, b1,
                                                          nullptr, h1_hi, h1_lo);
    }

    // 5) GEMM2: [s2|z2] = h1 [Ws2;Wn2]^T (raw fp32)
    {
        Seg sA{h1_hi, h1_lo, w_hi + 65536, w_lo + 65536};
        gemm3<1, 256, 0><<<(N + 127) / 128, 512, DSMEM>>>(sA, sA, N, nullptr,
                                                          s2z2, nullptr, nullptr);
    }

    // 6) fused: out = relu(s2 + agg(z2) + b2)
    gather_out<<<(N * 32 + 255) / 256, 256>>>(s2z2, srt, off, b2, out, N);
}

// round 12
// speedup vs baseline: 1.1089x; 1.0655x over previous
#include <cuda_runtime.h>
#include <cuda_bf16.h>
#include <cstdint>

// ---------------- scratch (static device globals; no allocation allowed) ----
#define N_CAP   50176
#define E_CAP   1000448
#define MAXBLK  64

__device__ uint16_t g_x_hi [N_CAP * 128];
__device__ uint16_t g_x_lo [N_CAP * 128];
__device__ uint16_t g_a1_hi[N_CAP * 128];
__device__ uint16_t g_a1_lo[N_CAP * 128];
__device__ uint16_t g_h1_hi[N_CAP * 256];
__device__ uint16_t g_h1_lo[N_CAP * 256];
__device__ float    g_s2z2 [N_CAP * 256];   // [s2 | z2] fp32
__device__ uint16_t g_w_hi [131072];        // Ws1 | Wn1 | Ws2 | Wn2
__device__ uint16_t g_w_lo [131072];
__device__ int      g_cnt   [N_CAP];
__device__ int      g_off   [N_CAP + 1];
__device__ int      g_cursor[N_CAP];
__device__ int      g_srt   [E_CAP];
__device__ int      g_bsum  [MAXBLK];

// ---------------- small helpers ----------------------------------------------
__device__ __forceinline__ uint32_t smem_u32(const void* p) {
    uint32_t a;
    asm("{ .reg .u64 t; cvta.to.shared.u64 t, %1; cvt.u32.u64 %0, t; }"
        : "=r"(a) : "l"(p));
    return a;
}
__device__ __forceinline__ void hilo(float v, uint16_t& h, uint16_t& l) {
    __nv_bfloat16 hb = __float2bfloat16(v);
    __nv_bfloat16 lb = __float2bfloat16(v - __bfloat162float(hb));
    h = __bfloat16_as_ushort(hb);
    l = __bfloat16_as_ushort(lb);
}
__device__ __forceinline__ void ldsm_x4(uint32_t* r, uint32_t addr) {
    asm volatile("ldmatrix.sync.aligned.m8n8.x4.shared.b16 {%0,%1,%2,%3}, [%4];"
                 : "=r"(r[0]), "=r"(r[1]), "=r"(r[2]), "=r"(r[3]) : "r"(addr));
}
__device__ __forceinline__ void ldsm_x2(uint32_t* r, uint32_t addr) {
    asm volatile("ldmatrix.sync.aligned.m8n8.x2.shared.b16 {%0,%1}, [%2];"
                 : "=r"(r[0]), "=r"(r[1]) : "r"(addr));
}
__device__ __forceinline__ void mma_bf16(float* d, const uint32_t* a,
                                         const uint32_t* b) {
    asm volatile(
        "mma.sync.aligned.m16n8k16.row.col.f32.bf16.bf16.f32 "
        "{%0,%1,%2,%3}, {%4,%5,%6,%7}, {%8,%9}, {%0,%1,%2,%3};"
        : "+f"(d[0]), "+f"(d[1]), "+f"(d[2]), "+f"(d[3])
        : "r"(a[0]), "r"(a[1]), "r"(a[2]), "r"(a[3]), "r"(b[0]), "r"(b[1]));
}
__device__ __forceinline__ void cp16(uint32_t smem, const void* g, uint32_t sz) {
    asm volatile("cp.async.ca.shared.global [%0], [%1], 16, %2;"
                 :: "r"(smem), "l"(g), "r"(sz) : "memory");
}
#define CP_COMMIT() asm volatile("cp.async.commit_group;" ::: "memory")
#define CP_WAIT1()  asm volatile("cp.async.wait_group 1;" ::: "memory")
#define CP_WAIT0()  asm volatile("cp.async.wait_group 0;" ::: "memory")

// ---------------- CSR build ---------------------------------------------------
__global__ void zero_i4(int4* __restrict__ p, int n4) {
    int i = blockIdx.x * blockDim.x + threadIdx.x;
    if (i < n4) p[i] = make_int4(0, 0, 0, 0);
}

__global__ void count_kernel(const int* __restrict__ dst, int E, int N,
                             int* __restrict__ cnt) {
    int i = (blockIdx.x * blockDim.x + threadIdx.x) * 2;
    if (i + 1 < E) {
        int2 d2 = *reinterpret_cast<const int2*>(dst + i);
        atomicAdd(&cnt[min(max(d2.x, 0), N - 1)], 1);
        atomicAdd(&cnt[min(max(d2.y, 0), N - 1)], 1);
    } else if (i < E) {
        atomicAdd(&cnt[min(max(dst[i], 0), N - 1)], 1);
    }
}

__global__ void block_sum(const int* __restrict__ cnt, int N,
                          int* __restrict__ bsum) {
    __shared__ int sh[1024];
    int i = blockIdx.x * 1024 + threadIdx.x;
    sh[threadIdx.x] = (i < N) ? cnt[i] : 0;
    __syncthreads();
    for (int d = 512; d > 0; d >>= 1) {
        if (threadIdx.x < d) sh[threadIdx.x] += sh[threadIdx.x + d];
        __syncthreads();
    }
    if (threadIdx.x == 0) bsum[blockIdx.x] = sh[0];
}

__global__ void block_scan(const int* __restrict__ cnt,
                           const int* __restrict__ bsum,
                           int* __restrict__ off, int* __restrict__ cursor,
                           int N) {
    __shared__ int sh[1024];
    __shared__ int carry_s;
    int tid = threadIdx.x;
    if (tid == 0) {
        int a = 0;
        for (int i = 0; i < (int)blockIdx.x; i++) a += bsum[i];
        carry_s = a;
    }
    int i = blockIdx.x * 1024 + tid;
    int v = (i < N) ? cnt[i] : 0;
    sh[tid] = v;
    __syncthreads();
#pragma unroll
    for (int d = 1; d < 1024; d <<= 1) {
        int t = (tid >= d) ? sh[tid - d] : 0;
        __syncthreads();
        sh[tid] += t;
        __syncthreads();
    }
    int incl = sh[tid] + carry_s;
    if (i < N) {
        off[i + 1] = incl;
        cursor[i]  = incl - v;
    }
    if (blockIdx.x == 0 && tid == 0) off[0] = 0;
}

__global__ void scatter_kernel(const int* __restrict__ src,
                               const int* __restrict__ dst, int E, int N,
                               int* __restrict__ cursor, int* __restrict__ srt) {
    int i = (blockIdx.x * blockDim.x + threadIdx.x) * 2;
    if (i + 1 < E) {
        int2 s2 = *reinterpret_cast<const int2*>(src + i);
        int2 d2 = *reinterpret_cast<const int2*>(dst + i);
        int p0 = atomicAdd(&cursor[min(max(d2.x, 0), N - 1)], 1);
        srt[p0] = min(max(s2.x, 0), N - 1);
        int p1 = atomicAdd(&cursor[min(max(d2.y, 0), N - 1)], 1);
        srt[p1] = min(max(s2.y, 0), N - 1);
    } else if (i < E) {
        int p0 = atomicAdd(&cursor[min(max(dst[i], 0), N - 1)], 1);
        srt[p0] = min(max(src[i], 0), N - 1);
    }
}

// ---------------- fp32 -> bf16 hi/lo conversions ------------------------------
__global__ void conv_hilo(const float* __restrict__ s, uint16_t* __restrict__ hi,
                          uint16_t* __restrict__ lo, int n) {
    int i = blockIdx.x * blockDim.x + threadIdx.x;
    if (i < n) hilo(s[i], hi[i], lo[i]);
}

__global__ void conv_w(const float* __restrict__ w0, const float* __restrict__ w1,
                       const float* __restrict__ w2, const float* __restrict__ w3,
                       uint16_t* __restrict__ hi, uint16_t* __restrict__ lo) {
    int i = blockIdx.x * blockDim.x + threadIdx.x;
    if (i >= 131072) return;
    int which = i >> 15, idx = i & 32767;
    const float* w = (which == 0) ? w0 : (which == 1) ? w1
                   : (which == 2) ? w2 : w3;
    hilo(w[idx], hi[i], lo[i]);
}

// ---------------- gather aggregation (layer 1): x fp32 -> a1 hi/lo -------------
__global__ void gather1(const float* __restrict__ x,
                        const int* __restrict__ srt,
                        const int* __restrict__ off,
                        uint16_t* __restrict__ hi, uint16_t* __restrict__ lo,
                        int N) {
    int warp = (blockIdx.x * blockDim.x + threadIdx.x) >> 5;
    int lane = threadIdx.x & 31;
    if (warp >= N) return;
    int s0 = off[warp], s1 = off[warp + 1];

    float4 acc = make_float4(0.f, 0.f, 0.f, 0.f);
    int e = s0;
    // unroll x4 for MLP
    for (; e + 3 < s1; e += 4) {
        int sA = srt[e], sB = srt[e + 1], sC = srt[e + 2], sD = srt[e + 3];
        float4 a = *reinterpret_cast<const float4*>(x + (size_t)sA * 128 + lane * 4);
        float4 b = *reinterpret_cast<const float4*>(x + (size_t)sB * 128 + lane * 4);
        float4 c = *reinterpret_cast<const float4*>(x + (size_t)sC * 128 + lane * 4);
        float4 d = *reinterpret_cast<const float4*>(x + (size_t)sD * 128 + lane * 4);
        acc.x += (a.x + b.x) + (c.x + d.x);
        acc.y += (a.y + b.y) + (c.y + d.y);
        acc.z += (a.z + b.z) + (c.z + d.z);
        acc.w += (a.w + b.w) + (c.w + d.w);
    }
    for (; e < s1; e++) {
        int sA = srt[e];
        float4 a = *reinterpret_cast<const float4*>(x + (size_t)sA * 128 + lane * 4);
        acc.x += a.x; acc.y += a.y; acc.z += a.z; acc.w += a.w;
    }

    float r = (s1 > s0) ? 1.0f / (float)(s1 - s0) : 0.0f;
    acc.x *= r; acc.y *= r; acc.z *= r; acc.w *= r;

    uint16_t h0, l0, h1v, l1, h2, l2, h3, l3;
    hilo(acc.x, h0, l0); hilo(acc.y, h1v, l1);
    hilo(acc.z, h2, l2); hilo(acc.w, h3, l3);
    size_t base = (size_t)warp * 128 + lane * 4;
    *reinterpret_cast<uint2*>(hi + base) =
        make_uint2((uint32_t)h0 | ((uint32_t)h1v << 16),
                   (uint32_t)h2 | ((uint32_t)h3 << 16));
    *reinterpret_cast<uint2*>(lo + base) =
        make_uint2((uint32_t)l0 | ((uint32_t)l1 << 16),
                   (uint32_t)l2 | ((uint32_t)l3 << 16));
}

// ---------------- fused layer-2 finish: out = relu(s2 + agg(z2) + b2) ---------
__global__ void gather_out(const float* __restrict__ s2z2,
                           const int* __restrict__ srt,
                           const int* __restrict__ off,
                           const float* __restrict__ bias,
                           float* __restrict__ out, int N) {
    int warp = (blockIdx.x * blockDim.x + threadIdx.x) >> 5;
    int lane = threadIdx.x & 31;
    if (warp >= N) return;
    int s0 = off[warp], s1 = off[warp + 1];

    float4 acc = make_float4(0.f, 0.f, 0.f, 0.f);
    int e = s0;
    for (; e + 3 < s1; e += 4) {
        int sA = srt[e], sB = srt[e + 1], sC = srt[e + 2], sD = srt[e + 3];
        float4 a = *reinterpret_cast<const float4*>(
            s2z2 + (size_t)sA * 256 + 128 + lane * 4);
        float4 b = *reinterpret_cast<const float4*>(
            s2z2 + (size_t)sB * 256 + 128 + lane * 4);
        float4 c = *reinterpret_cast<const float4*>(
            s2z2 + (size_t)sC * 256 + 128 + lane * 4);
        float4 d = *reinterpret_cast<const float4*>(
            s2z2 + (size_t)sD * 256 + 128 + lane * 4);
        acc.x += (a.x + b.x) + (c.x + d.x);
        acc.y += (a.y + b.y) + (c.y + d.y);
        acc.z += (a.z + b.z) + (c.z + d.z);
        acc.w += (a.w + b.w) + (c.w + d.w);
    }
    for (; e < s1; e++) {
        int sA = srt[e];
        float4 a = *reinterpret_cast<const float4*>(
            s2z2 + (size_t)sA * 256 + 128 + lane * 4);
        acc.x += a.x; acc.y += a.y; acc.z += a.z; acc.w += a.w;
    }

    float r = (s1 > s0) ? 1.0f / (float)(s1 - s0) : 0.0f;
    float4 s = *reinterpret_cast<const float4*>(s2z2 + (size_t)warp * 256 + lane * 4);
    float4 b = *reinterpret_cast<const float4*>(bias + lane * 4);
    float4 o;
    o.x = fmaxf(s.x + acc.x * r + b.x, 0.f);
    o.y = fmaxf(s.y + acc.y * r + b.y, 0.f);
    o.z = fmaxf(s.z + acc.z * r + b.z, 0.f);
    o.w = fmaxf(s.w + acc.w * r + b.w, 0.f);
    *reinterpret_cast<float4*>(out + (size_t)warp * 128 + lane * 4) = o;
}

// ---------------- bf16x3 GEMM, cp.async double-buffered, occ 2 (R9 config) ----
struct Seg { const uint16_t *ahi, *alo, *bhi, *blo; };

#define T_BYTES 10240
#define STAGE   (4 * T_BYTES)

template <int NSEG, int SEGD, int OUTMODE>   // OUTMODE 0: raw fp32; 1: bias+relu->hilo
__global__ void __launch_bounds__(256, 2)
gemm3(Seg s0, Seg s1, int M, const float* __restrict__ bias,
      float* __restrict__ C, uint16_t* __restrict__ Chi,
      uint16_t* __restrict__ Clo, int ldc) {
    extern __shared__ char dsm[];
    uint32_t sb = smem_u32(dsm);

    int tid = threadIdx.x;
    int wid = tid >> 5;
    int lane = tid & 31;
    int rowBase = blockIdx.y * 128;
    int colBase = blockIdx.x * 128;
    int warp_m = (wid & 3) * 32;
    int warp_n = (wid >> 2) * 64;

    float acc[2][8][4] = {};

    constexpr int ITER_PER_SEG = SEGD / 32;
    constexpr int NITER = NSEG * ITER_PER_SEG;

    auto load_stage = [&](int it, int buf) {
        Seg sg = (NSEG == 1 || it < ITER_PER_SEG) ? s0 : s1;
        int kin = (it % ITER_PER_SEG) * 32;
        uint32_t sbase = sb + buf * STAGE;
#pragma unroll
        for (int h = 0; h < 2; h++) {
            int f  = tid + h * 256;
            int r  = f >> 2;
            int c8 = (f & 3) * 8;
            int gm = rowBase + r;
            uint32_t asz = (gm < M) ? 16u : 0u;
            int gmc = min(gm, M - 1);
            uint32_t so = sbase + (uint32_t)(r * 40 + c8) * 2;
            size_t ao = (size_t)gmc * SEGD + kin + c8;
            cp16(so,               sg.ahi + ao, asz);
            cp16(so + T_BYTES,     sg.alo + ao, asz);
            size_t bo = (size_t)(colBase + r) * SEGD + kin + c8;
            cp16(so + 2 * T_BYTES, sg.bhi + bo, 16);
            cp16(so + 3 * T_BYTES, sg.blo + bo, 16);
        }
        CP_COMMIT();
    };

    load_stage(0, 0);

    for (int it = 0; it < NITER; it++) {
        if (it + 1 < NITER) {
            load_stage(it + 1, (it + 1) & 1);
            CP_WAIT1();
        } else {
            CP_WAIT0();
        }
        __syncthreads();

        uint32_t sbase = sb + (it & 1) * STAGE;
        uint32_t asH = sbase, asL = sbase + T_BYTES;
        uint32_t bsH = sbase + 2 * T_BYTES, bsL = sbase + 3 * T_BYTES;

#pragma unroll
        for (int ks = 0; ks < 32; ks += 16) {
            uint32_t bH[8][2], bL[8][2];
#pragma unroll
            for (int nt = 0; nt < 8; nt++) {
                uint32_t roff = (uint32_t)((warp_n + nt * 8 + (lane & 7)) * 40 +
                                           ks + ((lane >> 3) & 1) * 8) * 2;
                ldsm_x2(bH[nt], bsH + roff);
                ldsm_x2(bL[nt], bsL + roff);
            }
#pragma unroll
            for (int mt = 0; mt < 2; mt++) {
                uint32_t aH[4], aL[4];
                uint32_t roff = (uint32_t)((warp_m + mt * 16 + (lane & 15)) * 40 +
                                           ks + (lane >> 4) * 8) * 2;
                ldsm_x4(aH, asH + roff);
                ldsm_x4(aL, asL + roff);
#pragma unroll
                for (int nt = 0; nt < 8; nt++) {
                    mma_bf16(acc[mt][nt], aH, bH[nt]);
                    mma_bf16(acc[mt][nt], aH, bL[nt]);
                    mma_bf16(acc[mt][nt], aL, bH[nt]);
                }
            }
        }
        __syncthreads();
    }

    // epilogue
#pragma unroll
    for (int mt = 0; mt < 2; mt++) {
        int gm0 = rowBase + warp_m + mt * 16 + (lane >> 2);
#pragma unroll
        for (int nt = 0; nt < 8; nt++) {
            int n = colBase + warp_n + nt * 8 + (lane & 3) * 2;
#pragma unroll
            for (int half = 0; half < 2; half++) {
                int gm = gm0 + half * 8;
                if (gm >= M) continue;
                float v0 = acc[mt][nt][half * 2 + 0];
                float v1 = acc[mt][nt][half * 2 + 1];
                if (OUTMODE == 1) {
                    v0 = fmaxf(v0 + bias[n], 0.f);
                    v1 = fmaxf(v1 + bias[n + 1], 0.f);
                    uint16_t h0, l0, h1v, l1;
                    hilo(v0, h0, l0); hilo(v1, h1v, l1);
                    *reinterpret_cast<uint32_t*>(Chi + (size_t)gm * ldc + n) =
                        (uint32_t)h0 | ((uint32_t)h1v << 16);
                    *reinterpret_cast<uint32_t*>(Clo + (size_t)gm * ldc + n) =
                        (uint32_t)l0 | ((uint32_t)l1 << 16);
                } else {
                    *reinterpret_cast<float2*>(C + (size_t)gm * ldc + n) =
                        make_float2(v0, v1);
                }
            }
        }
    }
}

// ---------------- launch -------------------------------------------------------
extern "C" void kernel_launch(void* const* d_in, const int* in_sizes, int n_in,
                              void* d_out, int out_size) {
    const float* x   = (const float*)d_in[0];
    const int*   ei  = (const int*)d_in[1];
    const float* Ws1 = (const float*)d_in[2];
    const float* Wn1 = (const float*)d_in[3];
    const float* b1  = (const float*)d_in[4];
    const float* Ws2 = (const float*)d_in[5];
    const float* Wn2 = (const float*)d_in[6];
    const float* b2  = (const float*)d_in[7];
    float*       out = (float*)d_out;

    const int H     = in_sizes[4];             // 256
    const int F_IN  = in_sizes[2] / H;         // 128
    const int N     = in_sizes[0] / F_IN;      // 50000
    const int E     = in_sizes[1] / 2;         // 800000

    const int* src = ei;
    const int* dst = ei + E;

    uint16_t *x_hi, *x_lo, *a1_hi, *a1_lo, *h1_hi, *h1_lo, *w_hi, *w_lo;
    float *s2z2;
    int *cnt, *off, *cursor, *srt, *bsum;
    cudaGetSymbolAddress((void**)&x_hi,  g_x_hi);
    cudaGetSymbolAddress((void**)&x_lo,  g_x_lo);
    cudaGetSymbolAddress((void**)&a1_hi, g_a1_hi);
    cudaGetSymbolAddress((void**)&a1_lo, g_a1_lo);
    cudaGetSymbolAddress((void**)&h1_hi, g_h1_hi);
    cudaGetSymbolAddress((void**)&h1_lo, g_h1_lo);
    cudaGetSymbolAddress((void**)&w_hi,  g_w_hi);
    cudaGetSymbolAddress((void**)&w_lo,  g_w_lo);
    cudaGetSymbolAddress((void**)&s2z2,  g_s2z2);
    cudaGetSymbolAddress((void**)&cnt,    g_cnt);
    cudaGetSymbolAddress((void**)&off,    g_off);
    cudaGetSymbolAddress((void**)&cursor, g_cursor);
    cudaGetSymbolAddress((void**)&srt,    g_srt);
    cudaGetSymbolAddress((void**)&bsum,   g_bsum);

    const int nb = (N + 1023) / 1024;
    const int DSMEM = 2 * STAGE;   // 81920

    cudaFuncSetAttribute(gemm3<2, 128, 1>,
                         cudaFuncAttributeMaxDynamicSharedMemorySize, DSMEM);
    cudaFuncSetAttribute(gemm3<1, 256, 0>,
                         cudaFuncAttributeMaxDynamicSharedMemorySize, DSMEM);

    // 1) CSR build
    zero_i4<<<(N / 4 + 255) / 256, 256>>>((int4*)cnt, N / 4);
    count_kernel<<<(E / 2 + 255) / 256, 256>>>(dst, E, N, cnt);
    block_sum<<<nb, 1024>>>(cnt, N, bsum);
    block_scan<<<nb, 1024>>>(cnt, bsum, off, cursor, N);
    scatter_kernel<<<(E / 2 + 255) / 256, 256>>>(src, dst, E, N, cursor, srt);

    // 2) hi/lo conversions
    conv_hilo<<<(N * F_IN + 255) / 256, 256>>>(x, x_hi, x_lo, N * F_IN);
    conv_w<<<512, 256>>>(Ws1, Wn1, Ws2, Wn2, w_hi, w_lo);

    // 3) layer-1 aggregation -> a1 hi/lo
    gather1<<<(N * 32 + 255) / 256, 256>>>(x, srt, off, a1_hi, a1_lo, N);

    // 4) GEMM1: h1 = relu(x Ws1^T + a1 Wn1^T + b1) -> h1 hi/lo (ldc = 256)
    {
        Seg sA{x_hi, x_lo, w_hi, w_lo};
        Seg sB{a1_hi, a1_lo, w_hi + 32768, w_lo + 32768};
        dim3 grid(H / 128, (N + 127) / 128);
        gemm3<2, 128, 1><<<grid, 256, DSMEM>>>(sA, sB, N, b1, nullptr,
                                               h1_hi, h1_lo, H);
    }

    // 5) GEMM2: [s2|z2] = h1 [Ws2;Wn2]^T (raw fp32, ldc = 256)
    {
        Seg sA{h1_hi, h1_lo, w_hi + 65536, w_lo + 65536};
        dim3 grid(2, (N + 127) / 128);
        gemm3<1, 256, 0><<<grid, 256, DSMEM>>>(sA, sA, N, nullptr, s2z2,
                                               nullptr, nullptr, 256);
    }

    // 6) fused: out = relu(s2 + agg(z2) + b2)
    gather_out<<<(N * 32 + 255) / 256, 256>>>(s2z2, srt, off, b2, out, N);
}

// round 13
// speedup vs baseline: 1.1213x; 1.0111x over previous
#include <cuda_runtime.h>
#include <cuda_bf16.h>
#include <cstdint>

// ---------------- scratch (static device globals; no allocation allowed) ----
#define N_CAP   50176
#define E_CAP   1000448
#define MAXBLK  64

__device__ uint16_t g_x_hi [N_CAP * 128];
__device__ uint16_t g_x_lo [N_CAP * 128];
__device__ uint16_t g_a1_hi[N_CAP * 128];
__device__ uint16_t g_a1_lo[N_CAP * 128];
__device__ uint16_t g_h1_hi[N_CAP * 256];
__device__ uint16_t g_h1_lo[N_CAP * 256];
__device__ float    g_s2z2 [N_CAP * 256];   // [s2 | z2] fp32
__device__ uint16_t g_w_hi [131072];        // Ws1 | Wn1 | Ws2 | Wn2
__device__ uint16_t g_w_lo [131072];
__device__ int      g_cnt   [N_CAP];
__device__ int      g_off   [N_CAP + 1];
__device__ int      g_cursor[N_CAP];
__device__ int      g_srt   [E_CAP];
__device__ int      g_bsum  [MAXBLK];

// ---------------- small helpers ----------------------------------------------
__device__ __forceinline__ uint32_t smem_u32(const void* p) {
    uint32_t a;
    asm("{ .reg .u64 t; cvta.to.shared.u64 t, %1; cvt.u32.u64 %0, t; }"
        : "=r"(a) : "l"(p));
    return a;
}
__device__ __forceinline__ void hilo(float v, uint16_t& h, uint16_t& l) {
    __nv_bfloat16 hb = __float2bfloat16(v);
    __nv_bfloat16 lb = __float2bfloat16(v - __bfloat162float(hb));
    h = __bfloat16_as_ushort(hb);
    l = __bfloat16_as_ushort(lb);
}
__device__ __forceinline__ void ldsm_x4(uint32_t* r, uint32_t addr) {
    asm volatile("ldmatrix.sync.aligned.m8n8.x4.shared.b16 {%0,%1,%2,%3}, [%4];"
                 : "=r"(r[0]), "=r"(r[1]), "=r"(r[2]), "=r"(r[3]) : "r"(addr));
}
__device__ __forceinline__ void ldsm_x2(uint32_t* r, uint32_t addr) {
    asm volatile("ldmatrix.sync.aligned.m8n8.x2.shared.b16 {%0,%1}, [%2];"
                 : "=r"(r[0]), "=r"(r[1]) : "r"(addr));
}
__device__ __forceinline__ void mma_bf16(float* d, const uint32_t* a,
                                         const uint32_t* b) {
    asm volatile(
        "mma.sync.aligned.m16n8k16.row.col.f32.bf16.bf16.f32 "
        "{%0,%1,%2,%3}, {%4,%5,%6,%7}, {%8,%9}, {%0,%1,%2,%3};"
        : "+f"(d[0]), "+f"(d[1]), "+f"(d[2]), "+f"(d[3])
        : "r"(a[0]), "r"(a[1]), "r"(a[2]), "r"(a[3]), "r"(b[0]), "r"(b[1]));
}
__device__ __forceinline__ void cp16(uint32_t smem, const void* g, uint32_t sz) {
    asm volatile("cp.async.ca.shared.global [%0], [%1], 16, %2;"
                 :: "r"(smem), "l"(g), "r"(sz) : "memory");
}
#define CP_COMMIT() asm volatile("cp.async.commit_group;" ::: "memory")
#define CP_WAIT1()  asm volatile("cp.async.wait_group 1;" ::: "memory")
#define CP_WAIT0()  asm volatile("cp.async.wait_group 0;" ::: "memory")

// ---------------- CSR build ---------------------------------------------------
__global__ void zero_i4(int4* __restrict__ p, int n4) {
    int i = blockIdx.x * blockDim.x + threadIdx.x;
    if (i < n4) p[i] = make_int4(0, 0, 0, 0);
}

__global__ void count_kernel(const int* __restrict__ dst, int E, int N,
                             int* __restrict__ cnt) {
    int i = (blockIdx.x * blockDim.x + threadIdx.x) * 2;
    if (i + 1 < E) {
        int2 d2 = *reinterpret_cast<const int2*>(dst + i);
        atomicAdd(&cnt[min(max(d2.x, 0), N - 1)], 1);
        atomicAdd(&cnt[min(max(d2.y, 0), N - 1)], 1);
    } else if (i < E) {
        atomicAdd(&cnt[min(max(dst[i], 0), N - 1)], 1);
    }
}

__global__ void block_sum(const int* __restrict__ cnt, int N,
                          int* __restrict__ bsum) {
    __shared__ int sh[1024];
    int i = blockIdx.x * 1024 + threadIdx.x;
    sh[threadIdx.x] = (i < N) ? cnt[i] : 0;
    __syncthreads();
    for (int d = 512; d > 0; d >>= 1) {
        if (threadIdx.x < d) sh[threadIdx.x] += sh[threadIdx.x + d];
        __syncthreads();
    }
    if (threadIdx.x == 0) bsum[blockIdx.x] = sh[0];
}

__global__ void block_scan(const int* __restrict__ cnt,
                           const int* __restrict__ bsum,
                           int* __restrict__ off, int* __restrict__ cursor,
                           int N) {
    __shared__ int sh[1024];
    __shared__ int carry_s;
    int tid = threadIdx.x;
    if (tid == 0) {
        int a = 0;
        for (int i = 0; i < (int)blockIdx.x; i++) a += bsum[i];
        carry_s = a;
    }
    int i = blockIdx.x * 1024 + tid;
    int v = (i < N) ? cnt[i] : 0;
    sh[tid] = v;
    __syncthreads();
#pragma unroll
    for (int d = 1; d < 1024; d <<= 1) {
        int t = (tid >= d) ? sh[tid - d] : 0;
        __syncthreads();
        sh[tid] += t;
        __syncthreads();
    }
    int incl = sh[tid] + carry_s;
    if (i < N) {
        off[i + 1] = incl;
        cursor[i]  = incl - v;
    }
    if (blockIdx.x == 0 && tid == 0) off[0] = 0;
}

__global__ void scatter_kernel(const int* __restrict__ src,
                               const int* __restrict__ dst, int E, int N,
                               int* __restrict__ cursor, int* __restrict__ srt) {
    int i = (blockIdx.x * blockDim.x + threadIdx.x) * 2;
    if (i + 1 < E) {
        int2 s2 = *reinterpret_cast<const int2*>(src + i);
        int2 d2 = *reinterpret_cast<const int2*>(dst + i);
        int p0 = atomicAdd(&cursor[min(max(d2.x, 0), N - 1)], 1);
        srt[p0] = min(max(s2.x, 0), N - 1);
        int p1 = atomicAdd(&cursor[min(max(d2.y, 0), N - 1)], 1);
        srt[p1] = min(max(s2.y, 0), N - 1);
    } else if (i < E) {
        int p0 = atomicAdd(&cursor[min(max(dst[i], 0), N - 1)], 1);
        srt[p0] = min(max(src[i], 0), N - 1);
    }
}

// ---------------- fp32 -> bf16 hi/lo conversions ------------------------------
__global__ void conv_hilo(const float* __restrict__ s, uint16_t* __restrict__ hi,
                          uint16_t* __restrict__ lo, int n) {
    int i = blockIdx.x * blockDim.x + threadIdx.x;
    if (i < n) hilo(s[i], hi[i], lo[i]);
}

__global__ void conv_w(const float* __restrict__ w0, const float* __restrict__ w1,
                       const float* __restrict__ w2, const float* __restrict__ w3,
                       uint16_t* __restrict__ hi, uint16_t* __restrict__ lo) {
    int i = blockIdx.x * blockDim.x + threadIdx.x;
    if (i >= 131072) return;
    int which = i >> 15, idx = i & 32767;
    const float* w = (which == 0) ? w0 : (which == 1) ? w1
                   : (which == 2) ? w2 : w3;
    hilo(w[idx], hi[i], lo[i]);
}

// ---------------- gather aggregation (layer 1): x fp32 -> a1 hi/lo -------------
__global__ void gather1(const float* __restrict__ x,
                        const int* __restrict__ srt,
                        const int* __restrict__ off,
                        uint16_t* __restrict__ hi, uint16_t* __restrict__ lo,
                        int N) {
    int warp = (blockIdx.x * blockDim.x + threadIdx.x) >> 5;
    int lane = threadIdx.x & 31;
    if (warp >= N) return;
    int s0 = off[warp], s1 = off[warp + 1];

    float4 acc = make_float4(0.f, 0.f, 0.f, 0.f);
    int e = s0;
    for (; e + 3 < s1; e += 4) {
        int sA = srt[e], sB = srt[e + 1], sC = srt[e + 2], sD = srt[e + 3];
        float4 a = *reinterpret_cast<const float4*>(x + (size_t)sA * 128 + lane * 4);
        float4 b = *reinterpret_cast<const float4*>(x + (size_t)sB * 128 + lane * 4);
        float4 c = *reinterpret_cast<const float4*>(x + (size_t)sC * 128 + lane * 4);
        float4 d = *reinterpret_cast<const float4*>(x + (size_t)sD * 128 + lane * 4);
        acc.x += (a.x + b.x) + (c.x + d.x);
        acc.y += (a.y + b.y) + (c.y + d.y);
        acc.z += (a.z + b.z) + (c.z + d.z);
        acc.w += (a.w + b.w) + (c.w + d.w);
    }
    for (; e < s1; e++) {
        int sA = srt[e];
        float4 a = *reinterpret_cast<const float4*>(x + (size_t)sA * 128 + lane * 4);
        acc.x += a.x; acc.y += a.y; acc.z += a.z; acc.w += a.w;
    }

    float r = (s1 > s0) ? 1.0f / (float)(s1 - s0) : 0.0f;
    acc.x *= r; acc.y *= r; acc.z *= r; acc.w *= r;

    uint16_t h0, l0, h1v, l1, h2, l2, h3, l3;
    hilo(acc.x, h0, l0); hilo(acc.y, h1v, l1);
    hilo(acc.z, h2, l2); hilo(acc.w, h3, l3);
    size_t base = (size_t)warp * 128 + lane * 4;
    *reinterpret_cast<uint2*>(hi + base) =
        make_uint2((uint32_t)h0 | ((uint32_t)h1v << 16),
                   (uint32_t)h2 | ((uint32_t)h3 << 16));
    *reinterpret_cast<uint2*>(lo + base) =
        make_uint2((uint32_t)l0 | ((uint32_t)l1 << 16),
                   (uint32_t)l2 | ((uint32_t)l3 << 16));
}

// ---------------- fused layer-2 finish: out = relu(s2 + agg(z2) + b2) ---------
__global__ void gather_out(const float* __restrict__ s2z2,
                           const int* __restrict__ srt,
                           const int* __restrict__ off,
                           const float* __restrict__ bias,
                           float* __restrict__ out, int N) {
    int warp = (blockIdx.x * blockDim.x + threadIdx.x) >> 5;
    int lane = threadIdx.x & 31;
    if (warp >= N) return;
    int s0 = off[warp], s1 = off[warp + 1];

    float4 acc = make_float4(0.f, 0.f, 0.f, 0.f);
    int e = s0;
    for (; e + 3 < s1; e += 4) {
        int sA = srt[e], sB = srt[e + 1], sC = srt[e + 2], sD = srt[e + 3];
        float4 a = *reinterpret_cast<const float4*>(
            s2z2 + (size_t)sA * 256 + 128 + lane * 4);
        float4 b = *reinterpret_cast<const float4*>(
            s2z2 + (size_t)sB * 256 + 128 + lane * 4);
        float4 c = *reinterpret_cast<const float4*>(
            s2z2 + (size_t)sC * 256 + 128 + lane * 4);
        float4 d = *reinterpret_cast<const float4*>(
            s2z2 + (size_t)sD * 256 + 128 + lane * 4);
        acc.x += (a.x + b.x) + (c.x + d.x);
        acc.y += (a.y + b.y) + (c.y + d.y);
        acc.z += (a.z + b.z) + (c.z + d.z);
        acc.w += (a.w + b.w) + (c.w + d.w);
    }
    for (; e < s1; e++) {
        int sA = srt[e];
        float4 a = *reinterpret_cast<const float4*>(
            s2z2 + (size_t)sA * 256 + 128 + lane * 4);
        acc.x += a.x; acc.y += a.y; acc.z += a.z; acc.w += a.w;
    }

    float r = (s1 > s0) ? 1.0f / (float)(s1 - s0) : 0.0f;
    float4 s = *reinterpret_cast<const float4*>(s2z2 + (size_t)warp * 256 + lane * 4);
    float4 b = *reinterpret_cast<const float4*>(bias + lane * 4);
    float4 o;
    o.x = fmaxf(s.x + acc.x * r + b.x, 0.f);
    o.y = fmaxf(s.y + acc.y * r + b.y, 0.f);
    o.z = fmaxf(s.z + acc.z * r + b.z, 0.f);
    o.w = fmaxf(s.w + acc.w * r + b.w, 0.f);
    *reinterpret_cast<float4*>(out + (size_t)warp * 128 + lane * 4) = o;
}

// ---------------- bf16x3 GEMM, cp.async double-buffered, occ 2 ----------------
struct Seg { const uint16_t *ahi, *alo, *bhi, *blo; };

#define T_BYTES 10240
#define STAGE   (4 * T_BYTES)

template <int NSEG, int SEGD, int OUTMODE>   // OUTMODE 0: raw fp32; 1: bias+relu->hilo
__global__ void __launch_bounds__(256, 2)
gemm3(Seg s0, Seg s1, int M, const float* __restrict__ bias,
      float* __restrict__ C, uint16_t* __restrict__ Chi,
      uint16_t* __restrict__ Clo, int ldc) {
    extern __shared__ char dsm[];
    uint32_t sb = smem_u32(dsm);

    int tid = threadIdx.x;
    int wid = tid >> 5;
    int lane = tid & 31;
    int rowBase = blockIdx.y * 128;
    int colBase = blockIdx.x * 128;
    int warp_m = (wid & 3) * 32;
    int warp_n = (wid >> 2) * 64;

    float acc[2][8][4] = {};

    constexpr int ITER_PER_SEG = SEGD / 32;
    constexpr int NITER = NSEG * ITER_PER_SEG;

    auto load_stage = [&](int it, int buf) {
        Seg sg = (NSEG == 1 || it < ITER_PER_SEG) ? s0 : s1;
        int kin = (it % ITER_PER_SEG) * 32;
        uint32_t sbase = sb + buf * STAGE;
#pragma unroll
        for (int h = 0; h < 2; h++) {
            int f  = tid + h * 256;
            int r  = f >> 2;
            int c8 = (f & 3) * 8;
            int gm = rowBase + r;
            uint32_t asz = (gm < M) ? 16u : 0u;
            int gmc = min(gm, M - 1);
            uint32_t so = sbase + (uint32_t)(r * 40 + c8) * 2;
            size_t ao = (size_t)gmc * SEGD + kin + c8;
            cp16(so,               sg.ahi + ao, asz);
            cp16(so + T_BYTES,     sg.alo + ao, asz);
            size_t bo = (size_t)(colBase + r) * SEGD + kin + c8;
            cp16(so + 2 * T_BYTES, sg.bhi + bo, 16);
            cp16(so + 3 * T_BYTES, sg.blo + bo, 16);
        }
        CP_COMMIT();
    };

    load_stage(0, 0);

    for (int it = 0; it < NITER; it++) {
        if (it + 1 < NITER) {
            load_stage(it + 1, (it + 1) & 1);
            CP_WAIT1();
        } else {
            CP_WAIT0();
        }
        __syncthreads();

        uint32_t sbase = sb + (it & 1) * STAGE;
        uint32_t asH = sbase, asL = sbase + T_BYTES;
        uint32_t bsH = sbase + 2 * T_BYTES, bsL = sbase + 3 * T_BYTES;

#pragma unroll
        for (int ks = 0; ks < 32; ks += 16) {
            uint32_t bH[8][2], bL[8][2];
#pragma unroll
            for (int nt = 0; nt < 8; nt++) {
                uint32_t roff = (uint32_t)((warp_n + nt * 8 + (lane & 7)) * 40 +
                                           ks + ((lane >> 3) & 1) * 8) * 2;
                ldsm_x2(bH[nt], bsH + roff);
                ldsm_x2(bL[nt], bsL + roff);
            }
#pragma unroll
            for (int mt = 0; mt < 2; mt++) {
                uint32_t aH[4], aL[4];
                uint32_t roff = (uint32_t)((warp_m + mt * 16 + (lane & 15)) * 40 +
                                           ks + (lane >> 4) * 8) * 2;
                ldsm_x4(aH, asH + roff);
                ldsm_x4(aL, asL + roff);
#pragma unroll
                for (int nt = 0; nt < 8; nt++) {
                    mma_bf16(acc[mt][nt], aH, bH[nt]);
                    mma_bf16(acc[mt][nt], aH, bL[nt]);
                    mma_bf16(acc[mt][nt], aL, bH[nt]);
                }
            }
        }
        __syncthreads();
    }

    // epilogue
#pragma unroll
    for (int mt = 0; mt < 2; mt++) {
        int gm0 = rowBase + warp_m + mt * 16 + (lane >> 2);
#pragma unroll
        for (int nt = 0; nt < 8; nt++) {
            int n = colBase + warp_n + nt * 8 + (lane & 3) * 2;
#pragma unroll
            for (int half = 0; half < 2; half++) {
                int gm = gm0 + half * 8;
                if (gm >= M) continue;
                float v0 = acc[mt][nt][half * 2 + 0];
                float v1 = acc[mt][nt][half * 2 + 1];
                if (OUTMODE == 1) {
                    v0 = fmaxf(v0 + bias[n], 0.f);
                    v1 = fmaxf(v1 + bias[n + 1], 0.f);
                    uint16_t h0, l0, h1v, l1;
                    hilo(v0, h0, l0); hilo(v1, h1v, l1);
                    *reinterpret_cast<uint32_t*>(Chi + (size_t)gm * ldc + n) =
                        (uint32_t)h0 | ((uint32_t)h1v << 16);
                    *reinterpret_cast<uint32_t*>(Clo + (size_t)gm * ldc + n) =
                        (uint32_t)l0 | ((uint32_t)l1 << 16);
                } else {
                    *reinterpret_cast<float2*>(C + (size_t)gm * ldc + n) =
                        make_float2(v0, v1);
                }
            }
        }
    }
}

// ---------------- launch -------------------------------------------------------
extern "C" void kernel_launch(void* const* d_in, const int* in_sizes, int n_in,
                              void* d_out, int out_size) {
    const float* x   = (const float*)d_in[0];
    const int*   ei  = (const int*)d_in[1];
    const float* Ws1 = (const float*)d_in[2];
    const float* Wn1 = (const float*)d_in[3];
    const float* b1  = (const float*)d_in[4];
    const float* Ws2 = (const float*)d_in[5];
    const float* Wn2 = (const float*)d_in[6];
    const float* b2  = (const float*)d_in[7];
    float*       out = (float*)d_out;

    const int H     = in_sizes[4];             // 256
    const int F_IN  = in_sizes[2] / H;         // 128
    const int N     = in_sizes[0] / F_IN;      // 50000
    const int E     = in_sizes[1] / 2;         // 800000

    const int* src = ei;
    const int* dst = ei + E;

    uint16_t *x_hi, *x_lo, *a1_hi, *a1_lo, *h1_hi, *h1_lo, *w_hi, *w_lo;
    float *s2z2;
    int *cnt, *off, *cursor, *srt, *bsum;
    cudaGetSymbolAddress((void**)&x_hi,  g_x_hi);
    cudaGetSymbolAddress((void**)&x_lo,  g_x_lo);
    cudaGetSymbolAddress((void**)&a1_hi, g_a1_hi);
    cudaGetSymbolAddress((void**)&a1_lo, g_a1_lo);
    cudaGetSymbolAddress((void**)&h1_hi, g_h1_hi);
    cudaGetSymbolAddress((void**)&h1_lo, g_h1_lo);
    cudaGetSymbolAddress((void**)&w_hi,  g_w_hi);
    cudaGetSymbolAddress((void**)&w_lo,  g_w_lo);
    cudaGetSymbolAddress((void**)&s2z2,  g_s2z2);
    cudaGetSymbolAddress((void**)&cnt,    g_cnt);
    cudaGetSymbolAddress((void**)&off,    g_off);
    cudaGetSymbolAddress((void**)&cursor, g_cursor);
    cudaGetSymbolAddress((void**)&srt,    g_srt);
    cudaGetSymbolAddress((void**)&bsum,   g_bsum);

    // one-time infra (created outside graph capture on the correctness call)
    static cudaStream_t s2 = nullptr;
    static cudaEvent_t evF = nullptr, evJ = nullptr;
    if (!s2) {
        cudaStreamCreateWithFlags(&s2, cudaStreamNonBlocking);
        cudaEventCreateWithFlags(&evF, cudaEventDisableTiming);
        cudaEventCreateWithFlags(&evJ, cudaEventDisableTiming);
    }

    const int nb = (N + 1023) / 1024;
    const int DSMEM = 2 * STAGE;   // 81920

    cudaFuncSetAttribute(gemm3<2, 128, 1>,
                         cudaFuncAttributeMaxDynamicSharedMemorySize, DSMEM);
    cudaFuncSetAttribute(gemm3<1, 256, 0>,
                         cudaFuncAttributeMaxDynamicSharedMemorySize, DSMEM);

    // ---- fork: conversions on stream s2 (independent of the graph) ----
    cudaEventRecord(evF, 0);
    cudaStreamWaitEvent(s2, evF, 0);
    conv_hilo<<<(N * F_IN + 255) / 256, 256, 0, s2>>>(x, x_hi, x_lo, N * F_IN);
    conv_w<<<512, 256, 0, s2>>>(Ws1, Wn1, Ws2, Wn2, w_hi, w_lo);
    cudaEventRecord(evJ, s2);

    // ---- main stream: CSR build + layer-1 gather (overlaps with conv) ----
    zero_i4<<<(N / 4 + 255) / 256, 256>>>((int4*)cnt, N / 4);
    count_kernel<<<(E / 2 + 255) / 256, 256>>>(dst, E, N, cnt);
    block_sum<<<nb, 1024>>>(cnt, N, bsum);
    block_scan<<<nb, 1024>>>(cnt, bsum, off, cursor, N);
    scatter_kernel<<<(E / 2 + 255) / 256, 256>>>(src, dst, E, N, cursor, srt);
    gather1<<<(N * 32 + 255) / 256, 256>>>(x, srt, off, a1_hi, a1_lo, N);

    // ---- join before GEMM1 (needs x_hi/x_lo + weights) ----
    cudaStreamWaitEvent(0, evJ, 0);

    // GEMM1: h1 = relu(x Ws1^T + a1 Wn1^T + b1) -> h1 hi/lo (ldc = 256)
    {
        Seg sA{x_hi, x_lo, w_hi, w_lo};
        Seg sB{a1_hi, a1_lo, w_hi + 32768, w_lo + 32768};
        dim3 grid(H / 128, (N + 127) / 128);
        gemm3<2, 128, 1><<<grid, 256, DSMEM>>>(sA, sB, N, b1, nullptr,
                                               h1_hi, h1_lo, H);
    }

    // GEMM2: [s2|z2] = h1 [Ws2;Wn2]^T (raw fp32, ldc = 256)
    {
        Seg sA{h1_hi, h1_lo, w_hi + 65536, w_lo + 65536};
        dim3 grid(2, (N + 127) / 128);
        gemm3<1, 256, 0><<<grid, 256, DSMEM>>>(sA, sA, N, nullptr, s2z2,
                                               nullptr, nullptr, 256);
    }

    // fused: out = relu(s2 + agg(z2) + b2)
    gather_out<<<(N * 32 + 255) / 256, 256>>>(s2z2, srt, off, b2, out, N);
}